// round 8
// baseline (speedup 1.0000x reference)
#include <cuda_runtime.h>
#include <cuda_bf16.h>

// Fused GNN: 10 threads per element (one ring node per thread).
// Each 10-lane group inside a warp owns one batch element; lanes 30,31 of each
// warp are passengers (predicated off for stores, clamped for loads, but they
// execute all shfls so the full-warp mask is valid).
// Per-thread state: x float4, z 2x float4, z1[8], t -> ~55 regs, 32 warps/SM.
// Ring coupling via __shfl_sync with computed source lanes.

typedef unsigned long long u64;

static __device__ __forceinline__ u64 pk2(float a, float b) {
    u64 r; asm("mov.b64 %0, {%1, %2};" : "=l"(r) : "f"(a), "f"(b)); return r;
}
static __device__ __forceinline__ void upk2(u64 v, float& a, float& b) {
    asm("mov.b64 {%0, %1}, %2;" : "=f"(a), "=f"(b) : "l"(v));
}
static __device__ __forceinline__ u64 fma2(u64 a, u64 b, u64 c) {
    u64 d; asm("fma.rn.f32x2 %0, %1, %2, %3;" : "=l"(d) : "l"(a), "l"(b), "l"(c)); return d;
}
static __device__ __forceinline__ u64 add2(u64 a, u64 b) {
    u64 d; asm("add.rn.f32x2 %0, %1, %2;" : "=l"(d) : "l"(a), "l"(b)); return d;
}

__global__ void __launch_bounds__(128, 8) gnn_fused_kernel(
    const float* __restrict__ x,
    const float* __restrict__ z,
    const float* __restrict__ y,
    const float* __restrict__ enc_rel_w,
    const float* __restrict__ enc_rel_b,
    const float* __restrict__ enc_root_w,
    const float* __restrict__ pred_rel_w,
    const float* __restrict__ pred_rel_b,
    const float* __restrict__ pred_root_w,
    const float* __restrict__ dec_rel_w,
    const float* __restrict__ dec_rel_b,
    const float* __restrict__ dec_root_w,
    float* __restrict__ out,
    long long B)
{
    __shared__ __align__(16) u64 sWRt2[32];  // [g*4+p]: enc_root_w^T packed over f
    __shared__ __align__(16) u64 sW2[64];    // [(fp*8+g)*2 + {0:wa,1:wb}]
    __shared__ __align__(16) u64 sEW2[4], sEB2[4], sPB2[4];
    __shared__ float sDW[8];
    __shared__ float sDB, sDR;

    const int tid = threadIdx.x;
    if (tid < 32) {
        {
            const int g = tid >> 2, p = tid & 3;
            sWRt2[g * 4 + p] = pk2(enc_root_w[(2*p)*8 + g], enc_root_w[(2*p + 1)*8 + g]);
        }
        {
            const int fp = tid >> 3, g = tid & 7;
            const float w = expf(-1.0f / 9.0f);
            float pr0 = pred_rel_w[(2*fp)*8 + g],   pr1 = pred_rel_w[(2*fp + 1)*8 + g];
            float po0 = pred_root_w[(2*fp)*8 + g],  po1 = pred_root_w[(2*fp + 1)*8 + g];
            sW2[(fp*8 + g)*2 + 0] = pk2(pr0 + po0, pr1 + po1);   // wa
            sW2[(fp*8 + g)*2 + 1] = pk2(w * pr0, w * pr1);       // wb
        }
    }
    if (tid < 4) {
        sEW2[tid] = pk2(enc_rel_w[2*tid], enc_rel_w[2*tid + 1]);
        sEB2[tid] = pk2(enc_rel_b[2*tid], enc_rel_b[2*tid + 1]);
        sPB2[tid] = pk2(pred_rel_b[2*tid], pred_rel_b[2*tid + 1]);
    }
    if (tid < 8) sDW[tid] = dec_rel_w[tid];
    if (tid == 0) { sDB = dec_rel_b[0]; sDR = dec_root_w[0]; }
    __syncthreads();

    const int lane = tid & 31;
    const int grp  = lane / 10;          // 0..2 real, 3 = passenger (lanes 30,31)
    const int k    = lane - grp * 10;    // node index 0..9
    const long long warp_g = ((long long)blockIdx.x * blockDim.x + tid) >> 5;
    const long long e = warp_g * 3 + grp;
    const bool active = (grp < 3) && (e < B);
    const long long eL = (e < B) ? ((grp < 3) ? e : 0) : 0;   // clamped load index

    // shfl source lanes for ring neighbors (within the 10-lane group)
    const int srcm = lane + ((k == 0) ? 9 : -1);
    const int srcp = lane + ((k == 9) ? -9 : 1);

    // ---------- loads: x(1), z(2), y(1) float4 each, coalesced in-group ----------
    const float4 xv = reinterpret_cast<const float4*>(x)[eL * 10 + k];
    const float4 za = reinterpret_cast<const float4*>(z)[eL * 20 + 2*k];
    const float4 zb = reinterpret_cast<const float4*>(z)[eL * 20 + 2*k + 1];
    const float4 yv = reinterpret_cast<const float4*>(y)[eL * 10 + k];

    // ---------- s: needs prev node's x[1..3] ----------
    float m1 = __shfl_sync(0xFFFFFFFFu, xv.y, srcm);
    float m2 = __shfl_sync(0xFFFFFFFFu, xv.z, srcm);
    float m3 = __shfl_sync(0xFFFFFFFFu, xv.w, srcm);
    const float s = ((m1 + m2) + (m3 + xv.x)) + (xv.y + xv.z);

    // ---------- encoder: z1[f] for this node ----------
    float z1[8];
    {
        const ulonglong2* EW = reinterpret_cast<const ulonglong2*>(sEW2);
        const ulonglong2* EB = reinterpret_cast<const ulonglong2*>(sEB2);
        const ulonglong2* WR = reinterpret_cast<const ulonglong2*>(sWRt2);
        const float zv[8] = {za.x, za.y, za.z, za.w, zb.x, zb.y, zb.z, zb.w};
        u64 sk = pk2(s, s);
        ulonglong2 ew01 = EW[0], ew23 = EW[1];
        ulonglong2 eb01 = EB[0], eb23 = EB[1];
        u64 A0 = fma2(sk, ew01.x, eb01.x);
        u64 A1 = fma2(sk, ew01.y, eb01.y);
        u64 A2 = fma2(sk, ew23.x, eb23.x);
        u64 A3 = fma2(sk, ew23.y, eb23.y);
        #pragma unroll
        for (int g = 0; g < 8; g++) {
            ulonglong2 w01 = WR[g*2];
            ulonglong2 w23 = WR[g*2 + 1];
            u64 zg = pk2(zv[g], zv[g]);
            A0 = fma2(zg, w01.x, A0);
            A1 = fma2(zg, w01.y, A1);
            A2 = fma2(zg, w23.x, A2);
            A3 = fma2(zg, w23.y, A3);
        }
        float a, b;
        upk2(A0, a, b); z1[0] = fmaxf(a, 0.f); z1[1] = fmaxf(b, 0.f);
        upk2(A1, a, b); z1[2] = fmaxf(a, 0.f); z1[3] = fmaxf(b, 0.f);
        upk2(A2, a, b); z1[4] = fmaxf(a, 0.f); z1[5] = fmaxf(b, 0.f);
        upk2(A3, a, b); z1[6] = fmaxf(a, 0.f); z1[7] = fmaxf(b, 0.f);
    }

    // ---------- predictor + decoder-rel fused ----------
    float t = 0.0f;
    {
        const ulonglong2* W = reinterpret_cast<const ulonglong2*>(sW2);
        #pragma unroll
        for (int fp = 0; fp < 4; fp++) {
            u64 u2 = sPB2[fp];
            u64 v2 = 0ULL;
            #pragma unroll
            for (int g = 0; g < 8; g++) {
                ulonglong2 w = W[fp*8 + g];   // {wa, wb}
                u64 zg = pk2(z1[g], z1[g]);
                u2 = fma2(zg, w.x, u2);
                v2 = fma2(zg, w.y, v2);
            }
            // neighbor v from ring lanes (64-bit shfl = 2 hw shfls each)
            u64 vm = __shfl_sync(0xFFFFFFFFu, v2, srcm);
            u64 vp = __shfl_sync(0xFFFFFFFFu, v2, srcp);
            u64 pre = add2(u2, add2(vm, vp));
            float p0, p1; upk2(pre, p0, p1);
            t = fmaf(fmaxf(p0, 0.0f), sDW[2*fp],     t);
            t = fmaf(fmaxf(p1, 0.0f), sDW[2*fp + 1], t);
        }
    }

    // ---------- decoder: out[4k..4k+3] needs t[k], t[k+1] ----------
    const float tp = __shfl_sync(0xFFFFFFFFu, t, srcp);
    const float dB = sDB, dR = sDR;
    float4 r;
    r.x = fmaf(yv.x, dR, t + dB);
    r.y = fmaf(yv.y, dR, (t + tp) + dB);
    r.z = fmaf(yv.z, dR, (t + tp) + dB);
    r.w = fmaf(yv.w, dR, tp + dB);

    if (active) {
        reinterpret_cast<float4*>(out)[e * 10 + k] = r;
    }
}

extern "C" void kernel_launch(void* const* d_in, const int* in_sizes, int n_in,
                              void* d_out, int out_size) {
    const float* x           = (const float*)d_in[0];
    const float* z           = (const float*)d_in[1];
    const float* y           = (const float*)d_in[2];
    const float* enc_rel_w   = (const float*)d_in[3];
    const float* enc_rel_b   = (const float*)d_in[4];
    const float* enc_root_w  = (const float*)d_in[5];
    const float* pred_rel_w  = (const float*)d_in[6];
    const float* pred_rel_b  = (const float*)d_in[7];
    const float* pred_root_w = (const float*)d_in[8];
    const float* dec_rel_w   = (const float*)d_in[9];
    const float* dec_rel_b   = (const float*)d_in[10];
    const float* dec_root_w  = (const float*)d_in[11];
    float* out = (float*)d_out;

    const long long B = in_sizes[0] / 40;
    const long long warps  = (B + 2) / 3;          // 3 elements per warp
    const long long blocks = (warps + 3) / 4;      // 4 warps per block
    gnn_fused_kernel<<<(unsigned)blocks, 128>>>(
        x, z, y, enc_rel_w, enc_rel_b, enc_root_w,
        pred_rel_w, pred_rel_b, pred_root_w,
        dec_rel_w, dec_rel_b, dec_root_w, out, B);
}

// round 9
// speedup vs baseline: 1.5124x; 1.5124x over previous
#include <cuda_runtime.h>
#include <cuda_bf16.h>

// Fused GNN: 2 threads/element, f32x2 packed math (R5 skeleton).
// R9: z is NOT front-batched; the encoder k-loop carries a distance-2 rolling
// prefetch (2 LDG.128 per iteration), shrinking the per-thread LDG front batch
// from 15 to 9 and the live z registers from 40 to 24 -> 6 CTAs/SM.

typedef unsigned long long u64;

static __device__ __forceinline__ u64 pk2(float a, float b) {
    u64 r; asm("mov.b64 %0, {%1, %2};" : "=l"(r) : "f"(a), "f"(b)); return r;
}
static __device__ __forceinline__ void upk2(u64 v, float& a, float& b) {
    asm("mov.b64 {%0, %1}, %2;" : "=f"(a), "=f"(b) : "l"(v));
}
static __device__ __forceinline__ u64 fma2(u64 a, u64 b, u64 c) {
    u64 d; asm("fma.rn.f32x2 %0, %1, %2, %3;" : "=l"(d) : "l"(a), "l"(b), "l"(c)); return d;
}
static __device__ __forceinline__ u64 add2(u64 a, u64 b) {
    u64 d; asm("add.rn.f32x2 %0, %1, %2;" : "=l"(d) : "l"(a), "l"(b)); return d;
}

__global__ void __launch_bounds__(128, 6) gnn_fused_kernel(
    const float* __restrict__ x,
    const float* __restrict__ z,
    const float* __restrict__ y,
    const float* __restrict__ enc_rel_w,
    const float* __restrict__ enc_rel_b,
    const float* __restrict__ enc_root_w,
    const float* __restrict__ pred_rel_w,
    const float* __restrict__ pred_rel_b,
    const float* __restrict__ pred_root_w,
    const float* __restrict__ dec_rel_w,
    const float* __restrict__ dec_rel_b,
    const float* __restrict__ dec_root_w,
    float* __restrict__ out,
    long long NT)   // NT = 2*B threads
{
    __shared__ __align__(16) u64 sWRt2[32];  // [g*4+p]: enc_root_w^T packed over f
    __shared__ __align__(16) u64 sW2[64];    // [(fp*8+g)*2 + {0:wa,1:wb}]
    __shared__ __align__(16) u64 sEW2[4], sEB2[4], sPB2[4];
    __shared__ float sDW[8];
    __shared__ float sDB, sDR;

    const int tid = threadIdx.x;
    if (tid < 32) {
        {
            const int g = tid >> 2, p = tid & 3;
            sWRt2[g * 4 + p] = pk2(enc_root_w[(2*p)*8 + g], enc_root_w[(2*p + 1)*8 + g]);
        }
        {
            const int fp = tid >> 3, g = tid & 7;
            const float w = expf(-1.0f / 9.0f);
            float pr0 = pred_rel_w[(2*fp)*8 + g],   pr1 = pred_rel_w[(2*fp + 1)*8 + g];
            float po0 = pred_root_w[(2*fp)*8 + g],  po1 = pred_root_w[(2*fp + 1)*8 + g];
            sW2[(fp*8 + g)*2 + 0] = pk2(pr0 + po0, pr1 + po1);   // wa
            sW2[(fp*8 + g)*2 + 1] = pk2(w * pr0, w * pr1);       // wb
        }
    }
    if (tid < 4) {
        sEW2[tid] = pk2(enc_rel_w[2*tid], enc_rel_w[2*tid + 1]);
        sEB2[tid] = pk2(enc_rel_b[2*tid], enc_rel_b[2*tid + 1]);
        sPB2[tid] = pk2(pred_rel_b[2*tid], pred_rel_b[2*tid + 1]);
    }
    if (tid < 8) sDW[tid] = dec_rel_w[tid];
    if (tid == 0) { sDB = dec_rel_b[0]; sDR = dec_root_w[0]; }
    __syncthreads();

    const long long gt = (long long)blockIdx.x * blockDim.x + tid;
    if (gt >= NT) return;

    const float4* zp = reinterpret_cast<const float4*>(z) + gt * 10;

    // ---------- rolling z prefetch: nodes 0 and 1 in flight ----------
    float4 zb0 = zp[0], zb1 = zp[1];   // node k
    float4 zc0 = zp[2], zc1 = zp[3];   // node k+1

    // ---------- x loads + s[5] (overlaps z in flight) ----------
    float s[5];
    {
        float xl[20];
        const float4* xp = reinterpret_cast<const float4*>(x) + gt * 5;
        #pragma unroll
        for (int i = 0; i < 5; i++) {
            float4 v = xp[i];
            xl[4*i+0] = v.x; xl[4*i+1] = v.y; xl[4*i+2] = v.z; xl[4*i+3] = v.w;
        }
        float m0 = __shfl_xor_sync(0xFFFFFFFFu, xl[17], 1);
        float m1 = __shfl_xor_sync(0xFFFFFFFFu, xl[18], 1);
        float m2 = __shfl_xor_sync(0xFFFFFFFFu, xl[19], 1);
        s[0] = ((m0 + m1) + (m2 + xl[0])) + (xl[1] + xl[2]);
        #pragma unroll
        for (int k = 1; k < 5; k++) {
            float a0 = xl[4*k - 3] + xl[4*k - 2];
            float a1 = xl[4*k - 1] + xl[4*k + 0];
            float a2 = xl[4*k + 1] + xl[4*k + 2];
            s[k] = (a0 + a1) + a2;
        }
    }

    // ---------- encoder, k-outer with distance-2 prefetch ----------
    float z1[40];
    {
        const ulonglong2* EW = reinterpret_cast<const ulonglong2*>(sEW2);
        const ulonglong2* EB = reinterpret_cast<const ulonglong2*>(sEB2);
        const ulonglong2* WR = reinterpret_cast<const ulonglong2*>(sWRt2);
        ulonglong2 ew01 = EW[0], ew23 = EW[1];
        ulonglong2 eb01 = EB[0], eb23 = EB[1];
        #pragma unroll
        for (int k = 0; k < 5; k++) {
            // prefetch node k+2
            float4 zn0, zn1;
            if (k < 3) { zn0 = zp[2*k + 4]; zn1 = zp[2*k + 5]; }

            const float zv[8] = {zb0.x, zb0.y, zb0.z, zb0.w, zb1.x, zb1.y, zb1.z, zb1.w};
            u64 sk = pk2(s[k], s[k]);
            u64 A0 = fma2(sk, ew01.x, eb01.x);
            u64 A1 = fma2(sk, ew01.y, eb01.y);
            u64 A2 = fma2(sk, ew23.x, eb23.x);
            u64 A3 = fma2(sk, ew23.y, eb23.y);
            #pragma unroll
            for (int g = 0; g < 8; g++) {
                ulonglong2 w01 = WR[g*2];
                ulonglong2 w23 = WR[g*2 + 1];
                u64 zg = pk2(zv[g], zv[g]);
                A0 = fma2(zg, w01.x, A0);
                A1 = fma2(zg, w01.y, A1);
                A2 = fma2(zg, w23.x, A2);
                A3 = fma2(zg, w23.y, A3);
            }
            float a, b;
            upk2(A0, a, b); z1[k*8+0] = fmaxf(a, 0.f); z1[k*8+1] = fmaxf(b, 0.f);
            upk2(A1, a, b); z1[k*8+2] = fmaxf(a, 0.f); z1[k*8+3] = fmaxf(b, 0.f);
            upk2(A2, a, b); z1[k*8+4] = fmaxf(a, 0.f); z1[k*8+5] = fmaxf(b, 0.f);
            upk2(A3, a, b); z1[k*8+6] = fmaxf(a, 0.f); z1[k*8+7] = fmaxf(b, 0.f);

            // rotate pipeline
            zb0 = zc0; zb1 = zc1;
            zc0 = zn0; zc1 = zn1;
        }
    }

    // ---------- predictor + decoder-rel fused, (fp,g)-outer k-inner ----------
    float t[5] = {0.f, 0.f, 0.f, 0.f, 0.f};
    {
        const ulonglong2* W = reinterpret_cast<const ulonglong2*>(sW2);
        #pragma unroll
        for (int fp = 0; fp < 4; fp++) {
            u64 pb = sPB2[fp];
            u64 u2[5], v2[5];
            #pragma unroll
            for (int k = 0; k < 5; k++) { u2[k] = pb; v2[k] = 0ULL; }
            #pragma unroll
            for (int g = 0; g < 8; g++) {
                ulonglong2 w = W[fp*8 + g];   // {wa, wb}
                #pragma unroll
                for (int k = 0; k < 5; k++) {
                    u64 zg = pk2(z1[k*8 + g], z1[k*8 + g]);
                    u2[k] = fma2(zg, w.x, u2[k]);
                    v2[k] = fma2(zg, w.y, v2[k]);
                }
            }
            float va, vb;
            upk2(v2[4], va, vb);
            float vma = __shfl_xor_sync(0xFFFFFFFFu, va, 1);
            float vmb = __shfl_xor_sync(0xFFFFFFFFu, vb, 1);
            u64 vm2 = pk2(vma, vmb);
            upk2(v2[0], va, vb);
            float vpa = __shfl_xor_sync(0xFFFFFFFFu, va, 1);
            float vpb = __shfl_xor_sync(0xFFFFFFFFu, vb, 1);
            u64 vp2 = pk2(vpa, vpb);

            const float dw0 = sDW[2*fp], dw1 = sDW[2*fp + 1];
            #pragma unroll
            for (int k = 0; k < 5; k++) {
                u64 nb  = add2(k == 0 ? vm2 : v2[k-1], k == 4 ? vp2 : v2[k+1]);
                u64 pre = add2(u2[k], nb);
                float p0, p1; upk2(pre, p0, p1);
                t[k] = fmaf(fmaxf(p0, 0.0f), dw0, t[k]);
                t[k] = fmaf(fmaxf(p1, 0.0f), dw1, t[k]);
            }
        }
    }

    // ---------- decoder aggregation + root + output ----------
    float T[6];
    #pragma unroll
    for (int k = 0; k < 5; k++) T[k] = t[k];
    T[5] = __shfl_xor_sync(0xFFFFFFFFu, t[0], 1);

    const float dB = sDB, dR = sDR;
    const float4* yp = reinterpret_cast<const float4*>(y) + gt * 5;
    float4* op = reinterpret_cast<float4*>(out) + gt * 5;
    #pragma unroll
    for (int q = 0; q < 5; q++) {
        float4 yv = yp[q];
        float yc[4] = {yv.x, yv.y, yv.z, yv.w};
        float r[4];
        #pragma unroll
        for (int c = 0; c < 4; c++) {
            const int i = 4*q + c;
            const int lo = (i + 1) / 4;
            const int hi = (i + 3) / 4;
            float agg = T[lo];
            if (hi != lo) agg += T[hi];
            r[c] = fmaf(yc[c], dR, agg + dB);
        }
        op[q] = make_float4(r[0], r[1], r[2], r[3]);
    }
}

extern "C" void kernel_launch(void* const* d_in, const int* in_sizes, int n_in,
                              void* d_out, int out_size) {
    const float* x           = (const float*)d_in[0];
    const float* z           = (const float*)d_in[1];
    const float* y           = (const float*)d_in[2];
    const float* enc_rel_w   = (const float*)d_in[3];
    const float* enc_rel_b   = (const float*)d_in[4];
    const float* enc_root_w  = (const float*)d_in[5];
    const float* pred_rel_w  = (const float*)d_in[6];
    const float* pred_rel_b  = (const float*)d_in[7];
    const float* pred_root_w = (const float*)d_in[8];
    const float* dec_rel_w   = (const float*)d_in[9];
    const float* dec_rel_b   = (const float*)d_in[10];
    const float* dec_root_w  = (const float*)d_in[11];
    float* out = (float*)d_out;

    const long long B  = in_sizes[0] / 40;
    const long long NT = 2 * B;
    const int threads = 128;
    const long long blocks = (NT + threads - 1) / threads;
    gnn_fused_kernel<<<(unsigned)blocks, threads>>>(
        x, z, y, enc_rel_w, enc_rel_b, enc_root_w,
        pred_rel_w, pred_rel_b, pred_root_w,
        dec_rel_w, dec_rel_b, dec_root_w, out, NT);
}

// round 10
// speedup vs baseline: 1.5956x; 1.0550x over previous
#include <cuda_runtime.h>
#include <cuda_bf16.h>

// Fused GNN: 2 threads/element, f32x2 packed math (R5 skeleton — full z front
// batch preserved; that MLP is the proven binder).
// R10: 32-bit indexing + leaner x staging to fit 85 regs -> 6 CTAs/SM
// (24 warps) at UNCHANGED per-warp MLP.

typedef unsigned long long u64;

static __device__ __forceinline__ u64 pk2(float a, float b) {
    u64 r; asm("mov.b64 %0, {%1, %2};" : "=l"(r) : "f"(a), "f"(b)); return r;
}
static __device__ __forceinline__ void upk2(u64 v, float& a, float& b) {
    asm("mov.b64 {%0, %1}, %2;" : "=f"(a), "=f"(b) : "l"(v));
}
static __device__ __forceinline__ u64 fma2(u64 a, u64 b, u64 c) {
    u64 d; asm("fma.rn.f32x2 %0, %1, %2, %3;" : "=l"(d) : "l"(a), "l"(b), "l"(c)); return d;
}
static __device__ __forceinline__ u64 add2(u64 a, u64 b) {
    u64 d; asm("add.rn.f32x2 %0, %1, %2;" : "=l"(d) : "l"(a), "l"(b)); return d;
}

__global__ void __launch_bounds__(128, 6) gnn_fused_kernel(
    const float* __restrict__ x,
    const float* __restrict__ z,
    const float* __restrict__ y,
    const float* __restrict__ enc_rel_w,
    const float* __restrict__ enc_rel_b,
    const float* __restrict__ enc_root_w,
    const float* __restrict__ pred_rel_w,
    const float* __restrict__ pred_rel_b,
    const float* __restrict__ pred_root_w,
    const float* __restrict__ dec_rel_w,
    const float* __restrict__ dec_rel_b,
    const float* __restrict__ dec_root_w,
    float* __restrict__ out,
    int NT)   // NT = 2*B threads (fits int for B <= ~1e9/2)
{
    __shared__ __align__(16) u64 sWRt2[32];  // [g*4+p]: enc_root_w^T packed over f
    __shared__ __align__(16) u64 sW2[64];    // [(fp*8+g)*2 + {0:wa,1:wb}]
    __shared__ __align__(16) u64 sEW2[4], sEB2[4], sPB2[4];
    __shared__ float sDW[8];
    __shared__ float sDB, sDR;

    const int tid = threadIdx.x;
    if (tid < 32) {
        {
            const int g = tid >> 2, p = tid & 3;
            sWRt2[g * 4 + p] = pk2(enc_root_w[(2*p)*8 + g], enc_root_w[(2*p + 1)*8 + g]);
        }
        {
            const int fp = tid >> 3, g = tid & 7;
            const float w = expf(-1.0f / 9.0f);
            float pr0 = pred_rel_w[(2*fp)*8 + g],   pr1 = pred_rel_w[(2*fp + 1)*8 + g];
            float po0 = pred_root_w[(2*fp)*8 + g],  po1 = pred_root_w[(2*fp + 1)*8 + g];
            sW2[(fp*8 + g)*2 + 0] = pk2(pr0 + po0, pr1 + po1);   // wa
            sW2[(fp*8 + g)*2 + 1] = pk2(w * pr0, w * pr1);       // wb
        }
    }
    if (tid < 4) {
        sEW2[tid] = pk2(enc_rel_w[2*tid], enc_rel_w[2*tid + 1]);
        sEB2[tid] = pk2(enc_rel_b[2*tid], enc_rel_b[2*tid + 1]);
        sPB2[tid] = pk2(pred_rel_b[2*tid], pred_rel_b[2*tid + 1]);
    }
    if (tid < 8) sDW[tid] = dec_rel_w[tid];
    if (tid == 0) { sDB = dec_rel_b[0]; sDR = dec_root_w[0]; }
    __syncthreads();

    const int gt = blockIdx.x * blockDim.x + tid;
    if (gt >= NT) return;

    // ---------- coalesced front-batched loads (full MLP) ----------
    float4 c[5];
    {
        const float4* xp = reinterpret_cast<const float4*>(x) + gt * 5;
        #pragma unroll
        for (int i = 0; i < 5; i++) c[i] = xp[i];
    }
    float4 zl[10];
    {
        const float4* zp = reinterpret_cast<const float4*>(z) + gt * 10;
        #pragma unroll
        for (int i = 0; i < 10; i++) zl[i] = zp[i];
    }

    // ---------- s[5] straight from c[] ----------
    float s[5];
    {
        float m1 = __shfl_xor_sync(0xFFFFFFFFu, c[4].y, 1);
        float m2 = __shfl_xor_sync(0xFFFFFFFFu, c[4].z, 1);
        float m3 = __shfl_xor_sync(0xFFFFFFFFu, c[4].w, 1);
        s[0] = ((m1 + m2) + (m3 + c[0].x)) + (c[0].y + c[0].z);
        #pragma unroll
        for (int k = 1; k < 5; k++) {
            float a0 = c[k-1].y + c[k-1].z;
            float a1 = c[k-1].w + c[k].x;
            float a2 = c[k].y + c[k].z;
            s[k] = (a0 + a1) + a2;
        }
    }

    // ---------- encoder, k-outer: 4 packed accumulators per node ----------
    float z1[40];
    {
        const ulonglong2* EW = reinterpret_cast<const ulonglong2*>(sEW2);
        const ulonglong2* EB = reinterpret_cast<const ulonglong2*>(sEB2);
        const ulonglong2* WR = reinterpret_cast<const ulonglong2*>(sWRt2);
        ulonglong2 ew01 = EW[0], ew23 = EW[1];
        ulonglong2 eb01 = EB[0], eb23 = EB[1];
        #pragma unroll
        for (int k = 0; k < 5; k++) {
            float4 za = zl[2*k], zb = zl[2*k + 1];
            const float zv[8] = {za.x, za.y, za.z, za.w, zb.x, zb.y, zb.z, zb.w};
            u64 sk = pk2(s[k], s[k]);
            u64 A0 = fma2(sk, ew01.x, eb01.x);
            u64 A1 = fma2(sk, ew01.y, eb01.y);
            u64 A2 = fma2(sk, ew23.x, eb23.x);
            u64 A3 = fma2(sk, ew23.y, eb23.y);
            #pragma unroll
            for (int g = 0; g < 8; g++) {
                ulonglong2 w01 = WR[g*2];
                ulonglong2 w23 = WR[g*2 + 1];
                u64 zg = pk2(zv[g], zv[g]);
                A0 = fma2(zg, w01.x, A0);
                A1 = fma2(zg, w01.y, A1);
                A2 = fma2(zg, w23.x, A2);
                A3 = fma2(zg, w23.y, A3);
            }
            float a, b;
            upk2(A0, a, b); z1[k*8+0] = fmaxf(a, 0.f); z1[k*8+1] = fmaxf(b, 0.f);
            upk2(A1, a, b); z1[k*8+2] = fmaxf(a, 0.f); z1[k*8+3] = fmaxf(b, 0.f);
            upk2(A2, a, b); z1[k*8+4] = fmaxf(a, 0.f); z1[k*8+5] = fmaxf(b, 0.f);
            upk2(A3, a, b); z1[k*8+6] = fmaxf(a, 0.f); z1[k*8+7] = fmaxf(b, 0.f);
        }
    }

    // ---------- predictor + decoder-rel fused, (fp,g)-outer k-inner ----------
    float t[5] = {0.f, 0.f, 0.f, 0.f, 0.f};
    {
        const ulonglong2* W = reinterpret_cast<const ulonglong2*>(sW2);
        #pragma unroll
        for (int fp = 0; fp < 4; fp++) {
            u64 pb = sPB2[fp];
            u64 u2[5], v2[5];
            #pragma unroll
            for (int k = 0; k < 5; k++) { u2[k] = pb; v2[k] = 0ULL; }
            #pragma unroll
            for (int g = 0; g < 8; g++) {
                ulonglong2 w = W[fp*8 + g];   // {wa, wb}
                #pragma unroll
                for (int k = 0; k < 5; k++) {
                    u64 zg = pk2(z1[k*8 + g], z1[k*8 + g]);
                    u2[k] = fma2(zg, w.x, u2[k]);
                    v2[k] = fma2(zg, w.y, v2[k]);
                }
            }
            float va, vb;
            upk2(v2[4], va, vb);
            float vma = __shfl_xor_sync(0xFFFFFFFFu, va, 1);
            float vmb = __shfl_xor_sync(0xFFFFFFFFu, vb, 1);
            u64 vm2 = pk2(vma, vmb);
            upk2(v2[0], va, vb);
            float vpa = __shfl_xor_sync(0xFFFFFFFFu, va, 1);
            float vpb = __shfl_xor_sync(0xFFFFFFFFu, vb, 1);
            u64 vp2 = pk2(vpa, vpb);

            const float dw0 = sDW[2*fp], dw1 = sDW[2*fp + 1];
            #pragma unroll
            for (int k = 0; k < 5; k++) {
                u64 nb  = add2(k == 0 ? vm2 : v2[k-1], k == 4 ? vp2 : v2[k+1]);
                u64 pre = add2(u2[k], nb);
                float p0, p1; upk2(pre, p0, p1);
                t[k] = fmaf(fmaxf(p0, 0.0f), dw0, t[k]);
                t[k] = fmaf(fmaxf(p1, 0.0f), dw1, t[k]);
            }
        }
    }

    // ---------- decoder aggregation + root + output ----------
    float T[6];
    #pragma unroll
    for (int k = 0; k < 5; k++) T[k] = t[k];
    T[5] = __shfl_xor_sync(0xFFFFFFFFu, t[0], 1);

    const float dB = sDB, dR = sDR;
    const float4* yp = reinterpret_cast<const float4*>(y) + gt * 5;
    float4* op = reinterpret_cast<float4*>(out) + gt * 5;
    #pragma unroll
    for (int q = 0; q < 5; q++) {
        float4 yv = yp[q];
        float yc[4] = {yv.x, yv.y, yv.z, yv.w};
        float r[4];
        #pragma unroll
        for (int c2 = 0; c2 < 4; c2++) {
            const int i = 4*q + c2;
            const int lo = (i + 1) / 4;
            const int hi = (i + 3) / 4;
            float agg = T[lo];
            if (hi != lo) agg += T[hi];
            r[c2] = fmaf(yc[c2], dR, agg + dB);
        }
        op[q] = make_float4(r[0], r[1], r[2], r[3]);
    }
}

extern "C" void kernel_launch(void* const* d_in, const int* in_sizes, int n_in,
                              void* d_out, int out_size) {
    const float* x           = (const float*)d_in[0];
    const float* z           = (const float*)d_in[1];
    const float* y           = (const float*)d_in[2];
    const float* enc_rel_w   = (const float*)d_in[3];
    const float* enc_rel_b   = (const float*)d_in[4];
    const float* enc_root_w  = (const float*)d_in[5];
    const float* pred_rel_w  = (const float*)d_in[6];
    const float* pred_rel_b  = (const float*)d_in[7];
    const float* pred_root_w = (const float*)d_in[8];
    const float* dec_rel_w   = (const float*)d_in[9];
    const float* dec_rel_b   = (const float*)d_in[10];
    const float* dec_root_w  = (const float*)d_in[11];
    float* out = (float*)d_out;

    const int B  = in_sizes[0] / 40;
    const int NT = 2 * B;
    const int threads = 128;
    const int blocks = (NT + threads - 1) / threads;
    gnn_fused_kernel<<<blocks, threads>>>(
        x, z, y, enc_rel_w, enc_rel_b, enc_root_w,
        pred_rel_w, pred_rel_b, pred_root_w,
        dec_rel_w, dec_rel_b, dec_root_w, out, NT);
}